// round 13
// baseline (speedup 1.0000x reference)
#include <cuda_runtime.h>
#include <cstdint>

// ---------------- problem constants ----------------
#define NB 4
#define CDIM 384
#define CQ 192
#define IH 256
#define IW 256
#define H2 128
#define W2 128
#define NHEADS 8
#define HD 24
#define ATT_SCALE 0.2041241452319315f   // 24^-0.5

constexpr int HW  = IH * IW;   // 65536
constexpr int HW2 = H2 * W2;   // 16384

// ---------------- scratch (device globals; no runtime alloc) ----------------
__device__ float g_We[CDIM * CDIM];          // DWT-folded kv weights, tf32, row-major
__device__ float g_qw[CQ * CDIM];            // q weights, fragment-order tf32
__device__ float g_pw[CDIM * CQ];            // proj weights, fragment-order tf32
__device__ float g_qfeat[(size_t)NB * CQ * HW];
__device__ float g_kv[(size_t)NB * CDIM * HW2];
__device__ float g_feat[(size_t)NB * CQ * HW];

// ---------------- helpers ----------------
__device__ __forceinline__ uint32_t f2tf32(float f) {
    uint32_t r;
    asm("cvt.rna.tf32.f32 %0, %1;" : "=r"(r) : "f"(f));
    return r;
}
__device__ __forceinline__ uint32_t smem_u32(const void* p) {
    uint32_t a;
    asm("{ .reg .u64 t; cvta.to.shared.u64 t, %1; cvt.u32.u64 %0, t; }" : "=r"(a) : "l"(p));
    return a;
}
__device__ __forceinline__ void cp_async16(uint32_t dst, const float* src) {
    asm volatile("cp.async.ca.shared.global [%0], [%1], 16;"
                 :: "r"(dst), "l"(__cvta_generic_to_global(src)));
}
#define CP_COMMIT() asm volatile("cp.async.commit_group;" ::: "memory")
#define CP_WAIT0()  asm volatile("cp.async.wait_group 0;"  ::: "memory")

// m16n8k8 tf32 mma (baseline PTX, sm_80+)
__device__ __forceinline__ void mma8(float* c, const uint32_t* a, const uint32_t* b) {
    asm volatile(
        "mma.sync.aligned.m16n8k8.row.col.f32.tf32.tf32.f32 "
        "{%0,%1,%2,%3}, {%4,%5,%6,%7}, {%8,%9}, {%0,%1,%2,%3};"
        : "+f"(c[0]), "+f"(c[1]), "+f"(c[2]), "+f"(c[3])
        : "r"(a[0]), "r"(a[1]), "r"(a[2]), "r"(a[3]), "r"(b[0]), "r"(b[1]));
}

// ---------------- prep: fold Haar DWT into kv weights (tf32, row-major) --------
__global__ void prep_we_kernel(const float* __restrict__ kvw) {
    int idx = blockIdx.x * blockDim.x + threadIdx.x;
    if (idx >= CDIM * CDIM) return;
    int ch  = idx / CDIM;
    int rem = idx - ch * CDIM;
    int c4  = rem & ~3;
    int pos = rem & 3;
    const float* w = kvw + (size_t)ch * CDIM + c4;
    float a = w[0], b = w[1], c = w[2], d = w[3];
    float r;
    if      (pos == 0) r = 0.5f * ( a - b - c + d);
    else if (pos == 1) r = 0.5f * ( a - b + c - d);
    else if (pos == 2) r = 0.5f * ( a + b - c - d);
    else               r = 0.5f * ( a + b + c + d);
    g_We[idx] = __uint_as_float(f2tf32(r));
}

// ---------------- prep: rearrange weights into mma-fragment order + tf32 -------
// per M-block: [chunk c][tile = wmi*4+ks][lane][4 regs]
// reg order {(g,tig),(g+8,tig),(g,tig+4),(g+8,tig+4)}  (verified in R8 run)
template<int BM, int KTOT>
__global__ void prep_arrange(const float* __restrict__ src, float* __restrict__ dst, int mtot) {
    int idx = blockIdx.x * blockDim.x + threadIdx.x;
    if (idx >= mtot * KTOT) return;
    int mblk = idx / (BM * KTOT);
    int r    = idx % (BM * KTOT);
    int c    = r / (BM * 32);
    int t    = r % (BM * 32);
    int tile = t >> 7;
    int lane = (t >> 2) & 31;
    int qq   = t & 3;
    int wmi = tile >> 2, ks = tile & 3;
    int row = mblk * BM + wmi * 16 + (lane >> 2) + (qq & 1) * 8;
    int kk  = c * 32 + ks * 8 + (lane & 3) + (qq >> 1) * 4;
    dst[idx] = __uint_as_float(f2tf32(src[(size_t)row * KTOT + kk]));
}

// ---------------- tf32 mma.sync GEMM: Y[m,n] = sum_k W[m,k] X[k,n] (+bias) ------
// BN = 128. Warp tile 48 x (128/WARPS_N). B smem [32][136]: fragment bank =
// tig*8+g (bijection, conflict-free). A: AFRAG ? fragment-order LDS.128 :
// row-major [BM][36] 4xLDS.32 (both conflict-free). 2-stage cp.async pipeline.
// MODE 0: X = [K, N] row-major. MODE 1: kv fused DWT gather (full-row coalesced).
template<int WARPS_M, int KTOT, int MODE, int MTOT, bool BIAS, bool AFRAG, int MAXB>
__global__ __launch_bounds__(256, MAXB) void mma_gemm(
    const float* __restrict__ Wt, const float* __restrict__ X,
    float* __restrict__ Y, const float* __restrict__ bias, int N)
{
    constexpr int BM      = 48 * WARPS_M;            // 192 or 96
    constexpr int WARPS_N = 8 / WARPS_M;             // 2 or 4
    constexpr int WN      = 128 / WARPS_N;           // 64 or 32
    constexpr int NTW     = WN / 8;                  // 8 or 4
    constexpr int MT      = 3;
    constexpr int NCH     = KTOT / 32;
    constexpr int AFL     = AFRAG ? BM * 32 : BM * 36;
    constexpr int BUFL    = AFL + 32 * 136;

    extern __shared__ __align__(16) float sm[];
    const uint32_t sbase = smem_u32(sm);
    const int tid = threadIdx.x, wid = tid >> 5, lane = tid & 31;
    const int wm = wid / WARPS_N, wn = wid % WARPS_N;
    const int g = lane >> 2, tig = lane & 3;

    int mblk, nblk;
    if (MTOT > BM) { mblk = blockIdx.x; nblk = blockIdx.y; }
    else           { mblk = 0;          nblk = blockIdx.x; }
    const int n0 = nblk * 128;

    const float *Wp, *Xp;
    float* Yp;
    const float* bp = bias;
    int y2 = 0;

    if (MODE == 0) {
        int b = blockIdx.z;
        Wp = Wt + (size_t)mblk * BM * KTOT;
        Xp = X + (size_t)b * KTOT * N;
        Yp = Y + ((size_t)b * MTOT + mblk * BM) * N;
        if (BIAS) bp = bias + mblk * BM;
    } else {
        int b = blockIdx.z >> 2, gg = blockIdx.z & 3;
        Wp = Wt + (size_t)gg * BM * CDIM;
        Xp = X + ((size_t)b * CDIM + gg * 96) * HW;
        Yp = Y + ((size_t)b * CDIM + gg * 96) * HW2;
        y2 = nblk;                 // BN=128 = full W2 row
    }

    float acc[MT][NTW][4] = {};
    float4 bR[4];
    float  bS[16];

    auto loadA = [&](int c, int buf) {
        const uint32_t As = sbase + (uint32_t)buf * BUFL * 4;
        if (AFRAG) {
            const float* src = Wp + (size_t)c * (BM * 32);
            #pragma unroll
            for (int i = 0; i < BM / 32; i++) {
                int e = tid + i * 256;
                cp_async16(As + e * 16, src + e * 4);
            }
        } else {
            const int k0 = c * 32;
            #pragma unroll
            for (int i = 0; i < BM / 32; i++) {
                int e = tid + i * 256;
                int m = e >> 3, c4 = (e & 7) * 4;
                cp_async16(As + (m * 36 + c4) * 4, Wp + (size_t)m * KTOT + k0 + c4);
            }
        }
        CP_COMMIT();
    };

    auto loadB = [&](int c) {
        const int k0 = c * 32;
        if (MODE == 0) {
            #pragma unroll
            for (int i = 0; i < 4; i++) {
                int e = tid + i * 256;
                int kr = e >> 5, n4 = (e & 31) * 4;
                bR[i] = *(const float4*)(Xp + (size_t)(k0 + kr) * N + n0 + n4);
            }
        } else {
            const int crel0 = c * 8;
            #pragma unroll
            for (int i = 0; i < 16; i++) {
                int e = tid + i * 256;
                int ch = e >> 9, row = (e >> 8) & 1, col = e & 255;
                bS[i] = Xp[(size_t)(crel0 + ch) * HW + (2 * y2 + row) * IW + col];
            }
        }
    };

    auto storeB = [&](int buf) {
        uint32_t* Bs = (uint32_t*)(sm + buf * BUFL + AFL);
        if (MODE == 0) {
            #pragma unroll
            for (int i = 0; i < 4; i++) {
                int e = tid + i * 256;
                int kr = e >> 5, n4 = (e & 31) * 4;
                uint4 v;
                v.x = f2tf32(bR[i].x); v.y = f2tf32(bR[i].y);
                v.z = f2tf32(bR[i].z); v.w = f2tf32(bR[i].w);
                *(uint4*)(Bs + kr * 136 + n4) = v;
            }
        } else {
            #pragma unroll
            for (int i = 0; i < 16; i++) {
                int e = tid + i * 256;
                int ch = e >> 9, row = (e >> 8) & 1, col = e & 255;
                int k = ch * 4 + row * 2 + (col & 1);
                int n = col >> 1;
                Bs[k * 136 + n] = f2tf32(bS[i]);
            }
        }
    };

    auto compute = [&](int buf) {
        const uint32_t* As = (const uint32_t*)(sm + buf * BUFL);
        const uint32_t* Bs = As + AFL;
        #pragma unroll
        for (int ks = 0; ks < 4; ks++) {
            uint32_t a[MT][4], b[NTW][2];
            #pragma unroll
            for (int i = 0; i < MT; i++) {
                if (AFRAG) {
                    uint4 v = *(const uint4*)(As + (((wm * 3 + i) * 4 + ks) * 32 + lane) * 4);
                    a[i][0] = v.x; a[i][1] = v.y; a[i][2] = v.z; a[i][3] = v.w;
                } else {
                    const uint32_t* p = As + (wm * 48 + i * 16 + g) * 36 + ks * 8 + tig;
                    a[i][0] = p[0];
                    a[i][1] = p[8 * 36];
                    a[i][2] = p[4];
                    a[i][3] = p[8 * 36 + 4];
                }
            }
            #pragma unroll
            for (int j = 0; j < NTW; j++) {
                const uint32_t* p = Bs + (ks * 8 + tig) * 136 + wn * WN + j * 8 + g;
                b[j][0] = p[0];
                b[j][1] = p[4 * 136];
            }
            #pragma unroll
            for (int i = 0; i < MT; i++)
                #pragma unroll
                for (int j = 0; j < NTW; j++)
                    mma8(acc[i][j], a[i], b[j]);
        }
    };

    loadA(0, 0);
    loadB(0);
    storeB(0);
    CP_WAIT0();
    __syncthreads();
    for (int c = 0; c < NCH; c++) {
        if (c + 1 < NCH) { loadA(c + 1, (c + 1) & 1); loadB(c + 1); }
        compute(c & 1);
        if (c + 1 < NCH) {
            storeB((c + 1) & 1);
            CP_WAIT0();
            __syncthreads();
        }
    }

    // ---- epilogue ----
    const int mb = wm * 48;
    const int nb = n0 + wn * WN;
    #pragma unroll
    for (int i = 0; i < MT; i++) {
        int r0 = mb + i * 16 + g;
        float b0 = 0.f, b1 = 0.f;
        if (BIAS) { b0 = bp[r0]; b1 = bp[r0 + 8]; }
        #pragma unroll
        for (int j = 0; j < NTW; j++) {
            int nc = nb + j * 8 + tig * 2;
            *(float2*)(Yp + (size_t)r0 * N + nc) =
                make_float2(acc[i][j][0] + b0, acc[i][j][1] + b0);
            *(float2*)(Yp + (size_t)(r0 + 8) * N + nc) =
                make_float2(acc[i][j][2] + b1, acc[i][j][3] + b1);
        }
    }
}

// ---------------- attention: bilinear, register-blocked (proven core) ----------
constexpr int KS_F = 192 * 17;
constexpr int MS_F = 24 * 200;
constexpr int ATTN_SMEM = (2 * KS_F + MS_F) * 4;   // 45312 B

__global__ __launch_bounds__(256, 3) void attn_kernel()
{
    extern __shared__ float sm[];
    float* ks = sm;
    float* vs = ks + KS_F;
    float* Ms = vs + KS_F;

    const int w = blockIdx.x;
    const int b  = w >> 10;
    const int wl = w & 1023;
    const int wy = wl >> 5, wx = wl & 31;
    const int tid = threadIdx.x;

    const float* kvb = g_kv + (size_t)b * CDIM * HW2;
    #pragma unroll
    for (int i = 0; i < 12; i++) {
        int e = tid + i * 256;
        int ch = e >> 4, t = e & 15;
        int y2 = wy * 4 + (t >> 2), x2 = wx * 4 + (t & 3);
        size_t off = (size_t)ch * HW2 + y2 * W2 + x2;
        ks[ch * 17 + t] = kvb[off];
        vs[ch * 17 + t] = kvb[off + (size_t)CQ * HW2];
    }
    __syncthreads();

    {
        const int h = tid >> 5, lane = tid & 31;
        const int e0 = (lane >> 2) * 3, d0 = (lane & 3) * 6;
        float acc[3][6] = {};
        const float* kp = ks + (h * 24 + e0) * 17;
        const float* vp = vs + (h * 24 + d0) * 17;
        #pragma unroll
        for (int t = 0; t < 16; t++) {
            float kk[3], vv[6];
            #pragma unroll
            for (int i = 0; i < 3; i++) kk[i] = kp[i * 17 + t];
            #pragma unroll
            for (int j = 0; j < 6; j++) vv[j] = vp[j * 17 + t];
            #pragma unroll
            for (int i = 0; i < 3; i++)
                #pragma unroll
                for (int j = 0; j < 6; j++)
                    acc[i][j] = fmaf(kk[i], vv[j], acc[i][j]);
        }
        #pragma unroll
        for (int i = 0; i < 3; i++)
            #pragma unroll
            for (int j = 0; j < 6; j++)
                Ms[(e0 + i) * 200 + h * 25 + d0 + j] = acc[i][j] * ATT_SCALE;
    }
    __syncthreads();

    {
        const int q4 = tid >> 4;
        const int h  = (tid >> 1) & 7;
        const int dh = tid & 1;
        const int p0 = q4 * 4;
        const int y = wy * 8 + (p0 >> 3), x = wx * 8 + (p0 & 7);
        float acc[4][12] = {};
        const float* qp = g_qfeat + ((size_t)b * CQ + h * 24) * HW + y * IW + x;
        const float* mp = Ms + h * 25 + dh * 12;
        #pragma unroll
        for (int e = 0; e < 24; e++) {
            float4 qv = *(const float4*)(qp + (size_t)e * HW);
            float q0 = qv.x, q1 = qv.y, q2 = qv.z, q3 = qv.w;
            #pragma unroll
            for (int j = 0; j < 12; j++) {
                float mv = mp[e * 200 + j];
                acc[0][j] = fmaf(q0, mv, acc[0][j]);
                acc[1][j] = fmaf(q1, mv, acc[1][j]);
                acc[2][j] = fmaf(q2, mv, acc[2][j]);
                acc[3][j] = fmaf(q3, mv, acc[3][j]);
            }
        }
        float* fb = g_feat + ((size_t)b * CQ + h * 24 + dh * 12) * HW + y * IW + x;
        #pragma unroll
        for (int j = 0; j < 12; j++) {
            *(float4*)(fb + (size_t)j * HW) =
                make_float4(acc[0][j], acc[1][j], acc[2][j], acc[3][j]);
        }
    }
}

// ---------------- launch ----------------
extern "C" void kernel_launch(void* const* d_in, const int* in_sizes, int n_in,
                              void* d_out, int out_size) {
    const float* x      = (const float*)d_in[0];
    const float* q_w    = (const float*)d_in[1];
    const float* kv_w   = (const float*)d_in[2];
    const float* proj_w = (const float*)d_in[3];
    const float* proj_b = (const float*)d_in[4];
    float* out = (float*)d_out;

    float *qf, *kv, *ft, *we, *qw, *pw;
    cudaGetSymbolAddress((void**)&qf, g_qfeat);
    cudaGetSymbolAddress((void**)&kv, g_kv);
    cudaGetSymbolAddress((void**)&ft, g_feat);
    cudaGetSymbolAddress((void**)&we, g_We);
    cudaGetSymbolAddress((void**)&qw, g_qw);
    cudaGetSymbolAddress((void**)&pw, g_pw);

    auto kq = mma_gemm<4, 384, 0, 192, false, true,  1>;  // q:    BM=192, BN=128
    auto kk = mma_gemm<2, 384, 1,  96, false, false, 2>;  // kv:   BM=96,  BN=128
    auto kp = mma_gemm<4, 192, 0, 384, true,  true,  1>;  // proj: 2xBM=192, BN=128

    const int smem_q  = 2 * (192 * 32 + 32 * 136) * 4;  // 83968
    const int smem_kv = 2 * ( 96 * 36 + 32 * 136) * 4;  // 62464
    const int smem_pj = smem_q;

    static bool init_done = false;
    static cudaStream_t s1;
    static cudaEvent_t evFork, evJoin;
    if (!init_done) {
        cudaFuncSetAttribute(kq, cudaFuncAttributeMaxDynamicSharedMemorySize, smem_q);
        cudaFuncSetAttribute(kk, cudaFuncAttributeMaxDynamicSharedMemorySize, smem_kv);
        cudaFuncSetAttribute(kp, cudaFuncAttributeMaxDynamicSharedMemorySize, smem_pj);
        cudaFuncSetAttribute(attn_kernel, cudaFuncAttributeMaxDynamicSharedMemorySize, ATTN_SMEM);
        cudaStreamCreateWithFlags(&s1, cudaStreamNonBlocking);
        cudaEventCreateWithFlags(&evFork, cudaEventDisableTiming);
        cudaEventCreateWithFlags(&evJoin, cudaEventDisableTiming);
        init_done = true;
    }

    // prep (stream 0)
    prep_we_kernel<<<(CDIM * CDIM + 255) / 256, 256>>>(kv_w);
    prep_arrange<192, 384><<<(CQ * CDIM + 255) / 256, 256>>>(q_w, qw, CQ);
    prep_arrange<192, 192><<<(CDIM * CQ + 255) / 256, 256>>>(proj_w, pw, CDIM);

    // fork: kv on s1 concurrent with q on stream 0
    cudaEventRecord(evFork, 0);
    cudaStreamWaitEvent(s1, evFork, 0);
    kk<<<dim3(HW2 / 128, 1, NB * 4), 256, smem_kv, s1>>>(we, x, kv, nullptr, HW2);
    cudaEventRecord(evJoin, s1);

    kq<<<dim3(HW / 128, 1, NB), 256, smem_q>>>(qw, x, qf, nullptr, HW);

    // join: attn needs both qfeat (stream 0) and kv (s1)
    cudaStreamWaitEvent(0, evJoin, 0);
    attn_kernel<<<NB * 1024, 256, ATTN_SMEM>>>();
    kp<<<dim3(2, HW / 128, NB), 256, smem_pj>>>(pw, ft, out, proj_b, HW);
}

// round 14
// speedup vs baseline: 1.8018x; 1.8018x over previous
#include <cuda_runtime.h>
#include <cuda_fp16.h>
#include <cstdint>

// ---------------- problem constants ----------------
#define NB 4
#define CDIM 384
#define CQ 192
#define IH 256
#define IW 256
#define H2 128
#define W2 128
#define NHEADS 8
#define HD 24
#define ATT_SCALE 0.2041241452319315f   // 24^-0.5

constexpr int HW  = IH * IW;   // 65536
constexpr int HW2 = H2 * W2;   // 16384

// ---------------- scratch (device globals; no runtime alloc) ----------------
__device__ float    g_We[CDIM * CDIM];            // DWT-folded kv weights (fp32)
__device__ uint32_t g_qwh[CQ * CDIM / 2];         // q weights, fragment-order half2
__device__ uint32_t g_pwh[CDIM * CQ / 2];         // proj weights, fragment-order half2
__device__ uint32_t g_weh[CDIM * CDIM / 2];       // kv weights, fragment-order half2
__device__ float g_qfeat[(size_t)NB * CQ * HW];
__device__ float g_kv[(size_t)NB * CDIM * HW2];
__device__ float g_feat[(size_t)NB * CQ * HW];

// ---------------- helpers ----------------
__device__ __forceinline__ uint32_t smem_u32(const void* p) {
    uint32_t a;
    asm("{ .reg .u64 t; cvta.to.shared.u64 t, %1; cvt.u32.u64 %0, t; }" : "=r"(a) : "l"(p));
    return a;
}
__device__ __forceinline__ void cp_async16(uint32_t dst, const void* src) {
    asm volatile("cp.async.ca.shared.global [%0], [%1], 16;"
                 :: "r"(dst), "l"(__cvta_generic_to_global(src)));
}
#define CP_COMMIT() asm volatile("cp.async.commit_group;" ::: "memory")
#define CP_WAIT0()  asm volatile("cp.async.wait_group 0;"  ::: "memory")

__device__ __forceinline__ uint32_t packh2(float lo, float hi) {
    __half2 h = __floats2half2_rn(lo, hi);
    return *reinterpret_cast<uint32_t*>(&h);
}

// m16n8k16 fp16 mma, fp32 accumulate (baseline PTX, sm_80+)
__device__ __forceinline__ void mma16(float* c, const uint32_t* a, const uint32_t* b) {
    asm volatile(
        "mma.sync.aligned.m16n8k16.row.col.f32.f16.f16.f32 "
        "{%0,%1,%2,%3}, {%4,%5,%6,%7}, {%8,%9}, {%0,%1,%2,%3};"
        : "+f"(c[0]), "+f"(c[1]), "+f"(c[2]), "+f"(c[3])
        : "r"(a[0]), "r"(a[1]), "r"(a[2]), "r"(a[3]), "r"(b[0]), "r"(b[1]));
}

// ---------------- prep: fold Haar DWT into kv weights (fp32 out) ----------------
__global__ void prep_we_kernel(const float* __restrict__ kvw) {
    int idx = blockIdx.x * blockDim.x + threadIdx.x;
    if (idx >= CDIM * CDIM) return;
    int ch  = idx / CDIM;
    int rem = idx - ch * CDIM;
    int c4  = rem & ~3;
    int pos = rem & 3;
    const float* w = kvw + (size_t)ch * CDIM + c4;
    float a = w[0], b = w[1], c = w[2], d = w[3];
    float r;
    if      (pos == 0) r = 0.5f * ( a - b - c + d);
    else if (pos == 1) r = 0.5f * ( a - b + c - d);
    else if (pos == 2) r = 0.5f * ( a + b - c - d);
    else               r = 0.5f * ( a + b + c + d);
    g_We[idx] = r;
}

// ---------------- prep: weights -> fp16 fragment order --------------------------
// Per M-block (BM rows): [chunk c][tile = wmi*2+ks][lane][4 half2 words]
// word regs (m16n8k16 A): r0={A[g][k0],A[g][k0+1]}, r1=row g+8, r2=k0+8, r3=both.
template<int BM, int KTOT>
__global__ void prep_arrange_h(const float* __restrict__ src, uint32_t* __restrict__ dst,
                               int mtot) {
    int idx = blockIdx.x * blockDim.x + threadIdx.x;
    if (idx >= mtot * KTOT / 2) return;
    constexpr int WPB = BM * KTOT / 2;   // words per M-block
    constexpr int WPC = BM * 16;         // words per chunk
    int mblk = idx / WPB;
    int r    = idx % WPB;
    int c    = r / WPC;
    int t    = r % WPC;
    int tile = t >> 7;                   // 128 words per m16-tile-kstep
    int lane = (t >> 2) & 31;
    int q    = t & 3;
    int wmi = tile >> 1, ks = tile & 1;
    int row = mblk * BM + wmi * 16 + (lane >> 2) + (q & 1) * 8;
    int k   = c * 32 + ks * 16 + 2 * (lane & 3) + (q >> 1) * 8;
    const float* s = src + (size_t)row * KTOT + k;
    dst[idx] = packh2(s[0], s[1]);
}

// ---------------- fp16 mma GEMM: Y[m,n] = sum_k W[m,k] X[k,n] (+bias) -----------
// BN=64. A: fragment-order half2, cp.async linear, LDS.128 (conflict-free).
// B smem: half2 words [k2 0..15][72] — fragment bank 8*tig+g (bijection).
// 2-stage cp.async pipeline, 2 CTA/SM (R12-proven structure).
// MODE 0: X=[K,N] fp32 row-major. MODE 1: kv fused DWT gather (float2 coalesced).
template<int WARPS_M, int KTOT, int MODE, int MTOT, bool BIAS>
__global__ __launch_bounds__(256, 2) void hmma_gemm(
    const uint32_t* __restrict__ Wt, const float* __restrict__ X,
    float* __restrict__ Y, const float* __restrict__ bias, int N)
{
    constexpr int BM      = 48 * WARPS_M;            // 192 or 96
    constexpr int WARPS_N = 8 / WARPS_M;             // 2 or 4
    constexpr int WN      = 64 / WARPS_N;            // 32 or 16
    constexpr int NTW     = WN / 8;                  // 4 or 2
    constexpr int MT      = 3;
    constexpr int NCH     = KTOT / 32;
    constexpr int AW      = BM * 16;                 // A words per chunk
    constexpr int BW      = 16 * 72;                 // B words per chunk
    constexpr int BUFW    = AW + BW;
    constexpr int ACP     = AW / 4;                  // cp.async16 ops for A

    extern __shared__ __align__(16) uint32_t sw[];
    const uint32_t sbase = smem_u32(sw);
    const int tid = threadIdx.x, wid = tid >> 5, lane = tid & 31;
    const int wm = wid / WARPS_N, wn = wid % WARPS_N;
    const int g = lane >> 2, tig = lane & 3;

    const uint32_t* Wp;
    const float* Xp;
    float* Yp;
    const float* bp = bias;
    int y2 = 0, xb = 0;
    const int n0 = blockIdx.x * 64;

    if (MODE == 0) {
        int b = blockIdx.z, mblk = blockIdx.y;
        Wp = Wt + (size_t)mblk * (BM * KTOT / 2);
        Xp = X + (size_t)b * KTOT * N;
        Yp = Y + ((size_t)b * MTOT + mblk * BM) * N;
        if (BIAS) bp = bias + mblk * BM;
    } else {
        int b = blockIdx.z >> 2, gg = blockIdx.z & 3;
        Wp = Wt + (size_t)gg * (BM * KTOT / 2);
        Xp = X + ((size_t)b * CDIM + gg * 96) * HW;
        Yp = Y + ((size_t)b * CDIM + gg * 96) * HW2;
        y2 = n0 >> 7; xb = n0 & 127;
    }

    float acc[MT][NTW][4] = {};
    float4 bR0[2], bR1[2];
    float2 bS2[4];

    auto loadA = [&](int c, int buf) {
        const uint32_t As = sbase + (uint32_t)buf * BUFW * 4;
        const uint32_t* src = Wp + (size_t)c * AW;
        #pragma unroll
        for (int i = 0; i < (ACP + 255) / 256; i++) {
            int e = tid + i * 256;
            if (ACP % 256 == 0 || e < ACP)
                cp_async16(As + e * 16, src + e * 4);
        }
        CP_COMMIT();
    };

    auto loadB = [&](int c) {
        const int k0 = c * 32;
        if (MODE == 0) {
            // thread: k2 = tid>>4, n4 = (tid&15)*4; rows 2k2, 2k2+1
            int k2 = tid >> 4, n4 = (tid & 15) * 4;
            bR0[0] = *(const float4*)(Xp + (size_t)(k0 + 2 * k2)     * N + n0 + n4);
            bR1[0] = *(const float4*)(Xp + (size_t)(k0 + 2 * k2 + 1) * N + n0 + n4);
        } else {
            const int crel0 = c * 8;
            #pragma unroll
            for (int i = 0; i < 4; i++) {
                int e = tid + i * 256;            // 0..1023
                int ch = e >> 7, row = (e >> 6) & 1, c2 = e & 63;
                bS2[i] = *(const float2*)(Xp + (size_t)(crel0 + ch) * HW
                                          + (2 * y2 + row) * IW + 2 * xb + 2 * c2);
            }
        }
    };

    auto storeB = [&](int buf) {
        uint32_t* Bs = sw + buf * BUFW + AW;
        if (MODE == 0) {
            int k2 = tid >> 4, n4 = (tid & 15) * 4;
            uint4 v;
            v.x = packh2(bR0[0].x, bR1[0].x);
            v.y = packh2(bR0[0].y, bR1[0].y);
            v.z = packh2(bR0[0].z, bR1[0].z);
            v.w = packh2(bR0[0].w, bR1[0].w);
            *(uint4*)(Bs + k2 * 72 + n4) = v;
        } else {
            #pragma unroll
            for (int i = 0; i < 4; i++) {
                int e = tid + i * 256;
                int ch = e >> 7, row = (e >> 6) & 1, c2 = e & 63;
                int k2 = ch * 2 + row;
                Bs[k2 * 72 + c2] = packh2(bS2[i].x, bS2[i].y);
            }
        }
    };

    auto compute = [&](int buf) {
        const uint32_t* As = sw + buf * BUFW;
        const uint32_t* Bs = As + AW;
        #pragma unroll
        for (int ks = 0; ks < 2; ks++) {
            uint32_t a[MT][4], b[NTW][2];
            #pragma unroll
            for (int i = 0; i < MT; i++) {
                uint4 v = *(const uint4*)(As + (((wm * 3 + i) * 2 + ks) * 32 + lane) * 4);
                a[i][0] = v.x; a[i][1] = v.y; a[i][2] = v.z; a[i][3] = v.w;
            }
            #pragma unroll
            for (int j = 0; j < NTW; j++) {
                const uint32_t* p = Bs + (ks * 8 + tig) * 72 + wn * WN + j * 8 + g;
                b[j][0] = p[0];
                b[j][1] = p[4 * 72];
            }
            #pragma unroll
            for (int i = 0; i < MT; i++)
                #pragma unroll
                for (int j = 0; j < NTW; j++)
                    mma16(acc[i][j], a[i], b[j]);
        }
    };

    loadA(0, 0);
    loadB(0);
    storeB(0);
    CP_WAIT0();
    __syncthreads();
    for (int c = 0; c < NCH; c++) {
        if (c + 1 < NCH) { loadA(c + 1, (c + 1) & 1); loadB(c + 1); }
        compute(c & 1);
        if (c + 1 < NCH) {
            storeB((c + 1) & 1);
            CP_WAIT0();
            __syncthreads();
        }
    }

    // ---- epilogue (fp32) ----
    const int mb = wm * 48;
    const int nb = n0 + wn * WN;
    #pragma unroll
    for (int i = 0; i < MT; i++) {
        int r0 = mb + i * 16 + g;
        float b0 = 0.f, b1 = 0.f;
        if (BIAS) { b0 = bp[r0]; b1 = bp[r0 + 8]; }
        #pragma unroll
        for (int j = 0; j < NTW; j++) {
            int nc = nb + j * 8 + tig * 2;
            *(float2*)(Yp + (size_t)r0 * N + nc) =
                make_float2(acc[i][j][0] + b0, acc[i][j][1] + b0);
            *(float2*)(Yp + (size_t)(r0 + 8) * N + nc) =
                make_float2(acc[i][j][2] + b1, acc[i][j][3] + b1);
        }
    }
}

// ---------------- attention: bilinear, register-blocked (proven core) ----------
constexpr int KS_F = 192 * 17;
constexpr int MS_F = 24 * 200;
constexpr int ATTN_SMEM = (2 * KS_F + MS_F) * 4;   // 45312 B

__global__ __launch_bounds__(256, 3) void attn_kernel()
{
    extern __shared__ float sm[];
    float* ks = sm;
    float* vs = ks + KS_F;
    float* Ms = vs + KS_F;

    const int w = blockIdx.x;
    const int b  = w >> 10;
    const int wl = w & 1023;
    const int wy = wl >> 5, wx = wl & 31;
    const int tid = threadIdx.x;

    const float* kvb = g_kv + (size_t)b * CDIM * HW2;
    #pragma unroll
    for (int i = 0; i < 12; i++) {
        int e = tid + i * 256;
        int ch = e >> 4, t = e & 15;
        int y2 = wy * 4 + (t >> 2), x2 = wx * 4 + (t & 3);
        size_t off = (size_t)ch * HW2 + y2 * W2 + x2;
        ks[ch * 17 + t] = kvb[off];
        vs[ch * 17 + t] = kvb[off + (size_t)CQ * HW2];
    }
    __syncthreads();

    {
        const int h = tid >> 5, lane = tid & 31;
        const int e0 = (lane >> 2) * 3, d0 = (lane & 3) * 6;
        float acc[3][6] = {};
        const float* kp = ks + (h * 24 + e0) * 17;
        const float* vp = vs + (h * 24 + d0) * 17;
        #pragma unroll
        for (int t = 0; t < 16; t++) {
            float kk[3], vv[6];
            #pragma unroll
            for (int i = 0; i < 3; i++) kk[i] = kp[i * 17 + t];
            #pragma unroll
            for (int j = 0; j < 6; j++) vv[j] = vp[j * 17 + t];
            #pragma unroll
            for (int i = 0; i < 3; i++)
                #pragma unroll
                for (int j = 0; j < 6; j++)
                    acc[i][j] = fmaf(kk[i], vv[j], acc[i][j]);
        }
        #pragma unroll
        for (int i = 0; i < 3; i++)
            #pragma unroll
            for (int j = 0; j < 6; j++)
                Ms[(e0 + i) * 200 + h * 25 + d0 + j] = acc[i][j] * ATT_SCALE;
    }
    __syncthreads();

    {
        const int q4 = tid >> 4;
        const int h  = (tid >> 1) & 7;
        const int dh = tid & 1;
        const int p0 = q4 * 4;
        const int y = wy * 8 + (p0 >> 3), x = wx * 8 + (p0 & 7);
        float acc[4][12] = {};
        const float* qp = g_qfeat + ((size_t)b * CQ + h * 24) * HW + y * IW + x;
        const float* mp = Ms + h * 25 + dh * 12;
        #pragma unroll
        for (int e = 0; e < 24; e++) {
            float4 qv = *(const float4*)(qp + (size_t)e * HW);
            float q0 = qv.x, q1 = qv.y, q2 = qv.z, q3 = qv.w;
            #pragma unroll
            for (int j = 0; j < 12; j++) {
                float mv = mp[e * 200 + j];
                acc[0][j] = fmaf(q0, mv, acc[0][j]);
                acc[1][j] = fmaf(q1, mv, acc[1][j]);
                acc[2][j] = fmaf(q2, mv, acc[2][j]);
                acc[3][j] = fmaf(q3, mv, acc[3][j]);
            }
        }
        float* fb = g_feat + ((size_t)b * CQ + h * 24 + dh * 12) * HW + y * IW + x;
        #pragma unroll
        for (int j = 0; j < 12; j++) {
            *(float4*)(fb + (size_t)j * HW) =
                make_float4(acc[0][j], acc[1][j], acc[2][j], acc[3][j]);
        }
    }
}

// ---------------- launch ----------------
extern "C" void kernel_launch(void* const* d_in, const int* in_sizes, int n_in,
                              void* d_out, int out_size) {
    const float* x      = (const float*)d_in[0];
    const float* q_w    = (const float*)d_in[1];
    const float* kv_w   = (const float*)d_in[2];
    const float* proj_w = (const float*)d_in[3];
    const float* proj_b = (const float*)d_in[4];
    float* out = (float*)d_out;

    float *qf, *kv, *ft, *we;
    uint32_t *qwh, *pwh, *weh;
    cudaGetSymbolAddress((void**)&qf, g_qfeat);
    cudaGetSymbolAddress((void**)&kv, g_kv);
    cudaGetSymbolAddress((void**)&ft, g_feat);
    cudaGetSymbolAddress((void**)&we, g_We);
    cudaGetSymbolAddress((void**)&qwh, g_qwh);
    cudaGetSymbolAddress((void**)&pwh, g_pwh);
    cudaGetSymbolAddress((void**)&weh, g_weh);

    auto kq = hmma_gemm<4, 384, 0, 192, false>;   // q:    BM=192, K=384
    auto kk = hmma_gemm<2, 384, 1,  96, false>;   // kv:   BM=96,  K=384, DWT gather
    auto kp = hmma_gemm<4, 192, 0, 384, true>;    // proj: 2 x BM=192, K=192, bias

    const int smem_q  = 2 * (192 * 16 + 16 * 72) * 4;  // 33792
    const int smem_kv = 2 * ( 96 * 16 + 16 * 72) * 4;  // 21504
    const int smem_pj = smem_q;

    static bool init_done = false;
    static cudaStream_t s1;
    static cudaEvent_t evFork, evJoin;
    if (!init_done) {
        cudaFuncSetAttribute(kq, cudaFuncAttributeMaxDynamicSharedMemorySize, smem_q);
        cudaFuncSetAttribute(kk, cudaFuncAttributeMaxDynamicSharedMemorySize, smem_kv);
        cudaFuncSetAttribute(kp, cudaFuncAttributeMaxDynamicSharedMemorySize, smem_pj);
        cudaFuncSetAttribute(attn_kernel, cudaFuncAttributeMaxDynamicSharedMemorySize, ATTN_SMEM);
        cudaStreamCreateWithFlags(&s1, cudaStreamNonBlocking);
        cudaEventCreateWithFlags(&evFork, cudaEventDisableTiming);
        cudaEventCreateWithFlags(&evJoin, cudaEventDisableTiming);
        init_done = true;
    }

    // prep (stream 0)
    prep_we_kernel<<<(CDIM * CDIM + 255) / 256, 256>>>(kv_w);
    prep_arrange_h<192, 384><<<(CQ * CDIM / 2 + 255) / 256, 256>>>(q_w, qwh, CQ);
    prep_arrange_h<192, 192><<<(CDIM * CQ / 2 + 255) / 256, 256>>>(proj_w, pwh, CDIM);
    prep_arrange_h< 96, 384><<<(CDIM * CDIM / 2 + 255) / 256, 256>>>(we, weh, CDIM);

    // fork: kv on s1 concurrent with q on stream 0
    cudaEventRecord(evFork, 0);
    cudaStreamWaitEvent(s1, evFork, 0);
    kk<<<dim3(HW2 / 64, 1, NB * 4), 256, smem_kv, s1>>>(weh, x, kv, nullptr, HW2);
    cudaEventRecord(evJoin, s1);

    kq<<<dim3(HW / 64, 1, NB), 256, smem_q>>>(qwh, x, qf, nullptr, HW);

    // join: attn needs both qfeat (stream 0) and kv (s1)
    cudaStreamWaitEvent(0, evJoin, 0);
    attn_kernel<<<NB * 1024, 256, ATTN_SMEM>>>();
    kp<<<dim3(HW / 64, 2, NB), 256, smem_pj>>>(pwh, ft, out, proj_b, HW);
}

// round 15
// speedup vs baseline: 1.8972x; 1.0529x over previous
#include <cuda_runtime.h>
#include <cuda_fp16.h>
#include <cstdint>

// ---------------- problem constants ----------------
#define NB 4
#define CDIM 384
#define CQ 192
#define IH 256
#define IW 256
#define H2 128
#define W2 128
#define NHEADS 8
#define HD 24
#define ATT_SCALE 0.2041241452319315f   // 24^-0.5

constexpr int HW  = IH * IW;   // 65536
constexpr int HW2 = H2 * W2;   // 16384

// ---------------- scratch (device globals; no runtime alloc) ----------------
__device__ float    g_We[CDIM * CDIM];            // DWT-folded kv weights (fp32)
__device__ uint32_t g_qwh[CQ * CDIM / 2];         // q weights, fragment-order half2
__device__ uint32_t g_pwh[CDIM * CQ / 2];         // proj weights, fragment-order half2
__device__ uint32_t g_weh[CDIM * CDIM / 2];       // kv weights, fragment-order half2
__device__ uint32_t g_qfh[(size_t)NB * CQ * HW / 2];   // qfeat, half2 pixel-pairs (100MB)
__device__ float    g_kv[(size_t)NB * CDIM * HW2];     // kv, fp32
__device__ uint32_t g_fh[(size_t)NB * (CQ / 2) * HW];  // feat, half2 channel-pairs (100MB)

// ---------------- helpers ----------------
__device__ __forceinline__ uint32_t smem_u32(const void* p) {
    uint32_t a;
    asm("{ .reg .u64 t; cvta.to.shared.u64 t, %1; cvt.u32.u64 %0, t; }" : "=r"(a) : "l"(p));
    return a;
}
__device__ __forceinline__ void cp_async16(uint32_t dst, const void* src) {
    asm volatile("cp.async.ca.shared.global [%0], [%1], 16;"
                 :: "r"(dst), "l"(__cvta_generic_to_global(src)));
}
#define CP_COMMIT() asm volatile("cp.async.commit_group;" ::: "memory")
#define CP_WAIT0()  asm volatile("cp.async.wait_group 0;"  ::: "memory")

__device__ __forceinline__ uint32_t packh2(float lo, float hi) {
    __half2 h = __floats2half2_rn(lo, hi);
    return *reinterpret_cast<uint32_t*>(&h);
}

// m16n8k16 fp16 mma, fp32 accumulate (baseline PTX, sm_80+)
__device__ __forceinline__ void mma16(float* c, const uint32_t* a, const uint32_t* b) {
    asm volatile(
        "mma.sync.aligned.m16n8k16.row.col.f32.f16.f16.f32 "
        "{%0,%1,%2,%3}, {%4,%5,%6,%7}, {%8,%9}, {%0,%1,%2,%3};"
        : "+f"(c[0]), "+f"(c[1]), "+f"(c[2]), "+f"(c[3])
        : "r"(a[0]), "r"(a[1]), "r"(a[2]), "r"(a[3]), "r"(b[0]), "r"(b[1]));
}

// ---------------- prep: fold Haar DWT into kv weights (fp32 out) ----------------
__global__ void prep_we_kernel(const float* __restrict__ kvw) {
    int idx = blockIdx.x * blockDim.x + threadIdx.x;
    if (idx >= CDIM * CDIM) return;
    int ch  = idx / CDIM;
    int rem = idx - ch * CDIM;
    int c4  = rem & ~3;
    int pos = rem & 3;
    const float* w = kvw + (size_t)ch * CDIM + c4;
    float a = w[0], b = w[1], c = w[2], d = w[3];
    float r;
    if      (pos == 0) r = 0.5f * ( a - b - c + d);
    else if (pos == 1) r = 0.5f * ( a - b + c - d);
    else if (pos == 2) r = 0.5f * ( a + b - c - d);
    else               r = 0.5f * ( a + b + c + d);
    g_We[idx] = r;
}

// ---------------- prep: weights -> fp16 fragment order --------------------------
template<int BM, int KTOT>
__global__ void prep_arrange_h(const float* __restrict__ src, uint32_t* __restrict__ dst,
                               int mtot) {
    int idx = blockIdx.x * blockDim.x + threadIdx.x;
    if (idx >= mtot * KTOT / 2) return;
    constexpr int WPB = BM * KTOT / 2;
    constexpr int WPC = BM * 16;
    int mblk = idx / WPB;
    int r    = idx % WPB;
    int c    = r / WPC;
    int t    = r % WPC;
    int tile = t >> 7;
    int lane = (t >> 2) & 31;
    int q    = t & 3;
    int wmi = tile >> 1, ks = tile & 1;
    int row = mblk * BM + wmi * 16 + (lane >> 2) + (q & 1) * 8;
    int k   = c * 32 + ks * 16 + 2 * (lane & 3) + (q >> 1) * 8;
    const float* s = src + (size_t)row * KTOT + k;
    dst[idx] = packh2(s[0], s[1]);
}

// ---------------- fp16 mma GEMM -------------------------------------------------
// MODE 0: X fp32 [K,N] rows (register-staged B + packh2)
// MODE 1: kv fused DWT gather (register-staged)
// MODE 2: X half2 K-pair words [K/2][N] (pure cp.async B)
// OUTH: store output as half2 pixel-pair words (pitch N/2).
template<int WARPS_M, int KTOT, int MODE, int MTOT, bool BIAS, bool OUTH>
__global__ __launch_bounds__(256, 2) void hmma_gemm(
    const uint32_t* __restrict__ Wt, const float* __restrict__ X,
    float* __restrict__ Y, const float* __restrict__ bias, int N)
{
    constexpr int BM      = 48 * WARPS_M;
    constexpr int WARPS_N = 8 / WARPS_M;
    constexpr int WN      = 64 / WARPS_N;
    constexpr int NTW     = WN / 8;
    constexpr int MT      = 3;
    constexpr int NCH     = KTOT / 32;
    constexpr int AW      = BM * 16;
    constexpr int BW      = 16 * 72;
    constexpr int BUFW    = AW + BW;
    constexpr int ACP     = AW / 4;

    extern __shared__ __align__(16) uint32_t sw[];
    const uint32_t sbase = smem_u32(sw);
    const int tid = threadIdx.x, wid = tid >> 5, lane = tid & 31;
    const int wm = wid / WARPS_N, wn = wid % WARPS_N;
    const int g = lane >> 2, tig = lane & 3;

    const uint32_t* Wp;
    const float* Xp = nullptr;
    const uint32_t* Xw = nullptr;
    const float* bp = bias;
    size_t yoff = 0;
    int y2 = 0, xb = 0;
    const int n0 = blockIdx.x * 64;

    if (MODE == 0 || MODE == 2) {
        int b = blockIdx.z, mblk = blockIdx.y;
        Wp = Wt + (size_t)mblk * (BM * KTOT / 2);
        if (MODE == 0) Xp = X + (size_t)b * KTOT * N;
        else           Xw = (const uint32_t*)X + (size_t)b * (KTOT / 2) * N;
        yoff = ((size_t)b * MTOT + mblk * BM) * (OUTH ? N / 2 : N);
        if (BIAS) bp = bias + mblk * BM;
    } else {
        int b = blockIdx.z >> 2, gg = blockIdx.z & 3;
        Wp = Wt + (size_t)gg * (BM * KTOT / 2);
        Xp = X + ((size_t)b * CDIM + gg * 96) * HW;
        yoff = ((size_t)b * CDIM + gg * 96) * HW2;
        y2 = n0 >> 7; xb = n0 & 127;
    }

    float acc[MT][NTW][4] = {};
    float4 bR0, bR1;
    float2 bS2[4];

    auto loadA = [&](int c, int buf) {
        const uint32_t As = sbase + (uint32_t)buf * BUFW * 4;
        const uint32_t* src = Wp + (size_t)c * AW;
        #pragma unroll
        for (int i = 0; i < (ACP + 255) / 256; i++) {
            int e = tid + i * 256;
            if (ACP % 256 == 0 || e < ACP)
                cp_async16(As + e * 16, src + e * 4);
        }
        if (MODE == 2) {
            int k2 = tid >> 4, n4 = (tid & 15) * 4;
            cp_async16(As + (AW + k2 * 72 + n4) * 4,
                       Xw + (size_t)(c * 16 + k2) * N + n0 + n4);
        }
        CP_COMMIT();
    };

    auto loadB = [&](int c) {
        const int k0 = c * 32;
        if (MODE == 0) {
            int k2 = tid >> 4, n4 = (tid & 15) * 4;
            bR0 = *(const float4*)(Xp + (size_t)(k0 + 2 * k2)     * N + n0 + n4);
            bR1 = *(const float4*)(Xp + (size_t)(k0 + 2 * k2 + 1) * N + n0 + n4);
        } else if (MODE == 1) {
            const int crel0 = c * 8;
            #pragma unroll
            for (int i = 0; i < 4; i++) {
                int e = tid + i * 256;
                int ch = e >> 7, row = (e >> 6) & 1, c2 = e & 63;
                bS2[i] = *(const float2*)(Xp + (size_t)(crel0 + ch) * HW
                                          + (2 * y2 + row) * IW + 2 * xb + 2 * c2);
            }
        }
    };

    auto storeB = [&](int buf) {
        uint32_t* Bs = sw + buf * BUFW + AW;
        if (MODE == 0) {
            int k2 = tid >> 4, n4 = (tid & 15) * 4;
            uint4 v;
            v.x = packh2(bR0.x, bR1.x);
            v.y = packh2(bR0.y, bR1.y);
            v.z = packh2(bR0.z, bR1.z);
            v.w = packh2(bR0.w, bR1.w);
            *(uint4*)(Bs + k2 * 72 + n4) = v;
        } else if (MODE == 1) {
            #pragma unroll
            for (int i = 0; i < 4; i++) {
                int e = tid + i * 256;
                int ch = e >> 7, row = (e >> 6) & 1, c2 = e & 63;
                int k2 = ch * 2 + row;
                Bs[k2 * 72 + c2] = packh2(bS2[i].x, bS2[i].y);
            }
        }
    };

    auto compute = [&](int buf) {
        const uint32_t* As = sw + buf * BUFW;
        const uint32_t* Bs = As + AW;
        #pragma unroll
        for (int ks = 0; ks < 2; ks++) {
            uint32_t a[MT][4], b[NTW][2];
            #pragma unroll
            for (int i = 0; i < MT; i++) {
                uint4 v = *(const uint4*)(As + (((wm * 3 + i) * 2 + ks) * 32 + lane) * 4);
                a[i][0] = v.x; a[i][1] = v.y; a[i][2] = v.z; a[i][3] = v.w;
            }
            #pragma unroll
            for (int j = 0; j < NTW; j++) {
                const uint32_t* p = Bs + (ks * 8 + tig) * 72 + wn * WN + j * 8 + g;
                b[j][0] = p[0];
                b[j][1] = p[4 * 72];
            }
            #pragma unroll
            for (int i = 0; i < MT; i++)
                #pragma unroll
                for (int j = 0; j < NTW; j++)
                    mma16(acc[i][j], a[i], b[j]);
        }
    };

    loadA(0, 0);
    loadB(0);
    storeB(0);
    CP_WAIT0();
    __syncthreads();
    for (int c = 0; c < NCH; c++) {
        if (c + 1 < NCH) { loadA(c + 1, (c + 1) & 1); loadB(c + 1); }
        compute(c & 1);
        if (c + 1 < NCH) {
            storeB((c + 1) & 1);
            CP_WAIT0();
            __syncthreads();
        }
    }

    // ---- epilogue ----
    const int mb = wm * 48;
    const int nb = n0 + wn * WN;
    if (OUTH) {
        uint32_t* Yh = (uint32_t*)Y + yoff;
        #pragma unroll
        for (int i = 0; i < MT; i++) {
            int r0 = mb + i * 16 + g;
            #pragma unroll
            for (int j = 0; j < NTW; j++) {
                int ncw = (nb + j * 8) / 2 + tig;
                Yh[(size_t)r0 * (N / 2) + ncw]       = packh2(acc[i][j][0], acc[i][j][1]);
                Yh[(size_t)(r0 + 8) * (N / 2) + ncw] = packh2(acc[i][j][2], acc[i][j][3]);
            }
        }
    } else {
        float* Yp = Y + yoff;
        #pragma unroll
        for (int i = 0; i < MT; i++) {
            int r0 = mb + i * 16 + g;
            float b0 = 0.f, b1 = 0.f;
            if (BIAS) { b0 = bp[r0]; b1 = bp[r0 + 8]; }
            #pragma unroll
            for (int j = 0; j < NTW; j++) {
                int nc = nb + j * 8 + tig * 2;
                *(float2*)(Yp + (size_t)r0 * N + nc) =
                    make_float2(acc[i][j][0] + b0, acc[i][j][1] + b0);
                *(float2*)(Yp + (size_t)(r0 + 8) * N + nc) =
                    make_float2(acc[i][j][2] + b1, acc[i][j][3] + b1);
            }
        }
    }
}

// ---------------- attention: bilinear, register-blocked -------------------------
// Phase 2 (fp32 kv): M = scale*K^T V.  Phase 3: feat = q*M, q from half2
// pixel-pair words, feat written as half2 channel-pair words (proj B layout).
constexpr int KS_F = 192 * 17;
constexpr int MS_F = 24 * 200;
constexpr int ATTN_SMEM = (2 * KS_F + MS_F) * 4;   // 45312 B

__global__ __launch_bounds__(256, 3) void attn_kernel()
{
    extern __shared__ float sm[];
    float* ks = sm;
    float* vs = ks + KS_F;
    float* Ms = vs + KS_F;

    const int w = blockIdx.x;
    const int b  = w >> 10;
    const int wl = w & 1023;
    const int wy = wl >> 5, wx = wl & 31;
    const int tid = threadIdx.x;

    const float* kvb = g_kv + (size_t)b * CDIM * HW2;
    #pragma unroll
    for (int i = 0; i < 12; i++) {
        int e = tid + i * 256;
        int ch = e >> 4, t = e & 15;
        int y2 = wy * 4 + (t >> 2), x2 = wx * 4 + (t & 3);
        size_t off = (size_t)ch * HW2 + y2 * W2 + x2;
        ks[ch * 17 + t] = kvb[off];
        vs[ch * 17 + t] = kvb[off + (size_t)CQ * HW2];
    }
    __syncthreads();

    {
        const int h = tid >> 5, lane = tid & 31;
        const int e0 = (lane >> 2) * 3, d0 = (lane & 3) * 6;
        float acc[3][6] = {};
        const float* kp = ks + (h * 24 + e0) * 17;
        const float* vp = vs + (h * 24 + d0) * 17;
        #pragma unroll
        for (int t = 0; t < 16; t++) {
            float kk[3], vv[6];
            #pragma unroll
            for (int i = 0; i < 3; i++) kk[i] = kp[i * 17 + t];
            #pragma unroll
            for (int j = 0; j < 6; j++) vv[j] = vp[j * 17 + t];
            #pragma unroll
            for (int i = 0; i < 3; i++)
                #pragma unroll
                for (int j = 0; j < 6; j++)
                    acc[i][j] = fmaf(kk[i], vv[j], acc[i][j]);
        }
        #pragma unroll
        for (int i = 0; i < 3; i++)
            #pragma unroll
            for (int j = 0; j < 6; j++)
                Ms[(e0 + i) * 200 + h * 25 + d0 + j] = acc[i][j] * ATT_SCALE;
    }
    __syncthreads();

    {
        const int q4 = tid >> 4;
        const int h  = (tid >> 1) & 7;
        const int dh = tid & 1;
        const int p0 = q4 * 4;
        const int y = wy * 8 + (p0 >> 3), x = wx * 8 + (p0 & 7);
        float acc[4][12] = {};
        const uint32_t* qp = g_qfh + ((size_t)b * CQ + h * 24) * (HW / 2)
                             + ((y * IW + x) >> 1);
        const float* mp = Ms + h * 25 + dh * 12;
        #pragma unroll
        for (int e = 0; e < 24; e++) {
            uint2 wv = *(const uint2*)(qp + (size_t)e * (HW / 2));
            float2 f0 = __half22float2(*reinterpret_cast<__half2*>(&wv.x));
            float2 f1 = __half22float2(*reinterpret_cast<__half2*>(&wv.y));
            float q0 = f0.x, q1 = f0.y, q2 = f1.x, q3 = f1.y;
            #pragma unroll
            for (int j = 0; j < 12; j++) {
                float mv = mp[e * 200 + j];
                acc[0][j] = fmaf(q0, mv, acc[0][j]);
                acc[1][j] = fmaf(q1, mv, acc[1][j]);
                acc[2][j] = fmaf(q2, mv, acc[2][j]);
                acc[3][j] = fmaf(q3, mv, acc[3][j]);
            }
        }
        // feat: half2 channel-pair words, row = channel pair, col = pixel
        uint32_t* fb = g_fh + ((size_t)b * (CQ / 2) + (h * 24 + dh * 12) / 2) * HW
                       + y * IW + x;
        #pragma unroll
        for (int jp = 0; jp < 6; jp++) {
            uint4 wv;
            wv.x = packh2(acc[0][2 * jp], acc[0][2 * jp + 1]);
            wv.y = packh2(acc[1][2 * jp], acc[1][2 * jp + 1]);
            wv.z = packh2(acc[2][2 * jp], acc[2][2 * jp + 1]);
            wv.w = packh2(acc[3][2 * jp], acc[3][2 * jp + 1]);
            *(uint4*)(fb + (size_t)jp * HW) = wv;
        }
    }
}

// ---------------- launch ----------------
extern "C" void kernel_launch(void* const* d_in, const int* in_sizes, int n_in,
                              void* d_out, int out_size) {
    const float* x      = (const float*)d_in[0];
    const float* q_w    = (const float*)d_in[1];
    const float* kv_w   = (const float*)d_in[2];
    const float* proj_w = (const float*)d_in[3];
    const float* proj_b = (const float*)d_in[4];
    float* out = (float*)d_out;

    float *kv, *we;
    uint32_t *qwh, *pwh, *weh, *qfh, *fh;
    cudaGetSymbolAddress((void**)&kv, g_kv);
    cudaGetSymbolAddress((void**)&we, g_We);
    cudaGetSymbolAddress((void**)&qwh, g_qwh);
    cudaGetSymbolAddress((void**)&pwh, g_pwh);
    cudaGetSymbolAddress((void**)&weh, g_weh);
    cudaGetSymbolAddress((void**)&qfh, g_qfh);
    cudaGetSymbolAddress((void**)&fh, g_fh);

    auto kq = hmma_gemm<4, 384, 0, 192, false, true >;  // q -> half2 qfeat
    auto kk = hmma_gemm<2, 384, 1,  96, false, false>;  // kv -> fp32
    auto kp = hmma_gemm<4, 192, 2, 384, true,  false>;  // proj: B = half2 feat words

    const int smem_g = 2 * (192 * 16 + 16 * 72) * 4;   // 33792
    const int smem_kv = 2 * (96 * 16 + 16 * 72) * 4;   // 21504

    static bool init_done = false;
    static cudaStream_t s1;
    static cudaEvent_t evFork, evJoin;
    if (!init_done) {
        cudaFuncSetAttribute(kq, cudaFuncAttributeMaxDynamicSharedMemorySize, smem_g);
        cudaFuncSetAttribute(kk, cudaFuncAttributeMaxDynamicSharedMemorySize, smem_kv);
        cudaFuncSetAttribute(kp, cudaFuncAttributeMaxDynamicSharedMemorySize, smem_g);
        cudaFuncSetAttribute(attn_kernel, cudaFuncAttributeMaxDynamicSharedMemorySize, ATTN_SMEM);
        cudaStreamCreateWithFlags(&s1, cudaStreamNonBlocking);
        cudaEventCreateWithFlags(&evFork, cudaEventDisableTiming);
        cudaEventCreateWithFlags(&evJoin, cudaEventDisableTiming);
        init_done = true;
    }

    // prep (stream 0)
    prep_we_kernel<<<(CDIM * CDIM + 255) / 256, 256>>>(kv_w);
    prep_arrange_h<192, 384><<<(CQ * CDIM / 2 + 255) / 256, 256>>>(q_w, qwh, CQ);
    prep_arrange_h<192, 192><<<(CDIM * CQ / 2 + 255) / 256, 256>>>(proj_w, pwh, CDIM);
    prep_arrange_h< 96, 384><<<(CDIM * CDIM / 2 + 255) / 256, 256>>>(we, weh, CDIM);

    // fork: kv on s1 concurrent with q on stream 0
    cudaEventRecord(evFork, 0);
    cudaStreamWaitEvent(s1, evFork, 0);
    kk<<<dim3(HW2 / 64, 1, NB * 4), 256, smem_kv, s1>>>(weh, x, kv, nullptr, HW2);
    cudaEventRecord(evJoin, s1);

    kq<<<dim3(HW / 64, 1, NB), 256, smem_g>>>(qwh, x, (float*)qfh, nullptr, HW);

    // join: attn needs both qfeat (stream 0) and kv (s1)
    cudaStreamWaitEvent(0, evJoin, 0);
    attn_kernel<<<NB * 1024, 256, ATTN_SMEM>>>();
    kp<<<dim3(HW / 64, 2, NB), 256, smem_g>>>(pwh, (const float*)fh, out, proj_b, HW);
}